// round 1
// baseline (speedup 1.0000x reference)
#include <cuda_runtime.h>
#include <math.h>

// Problem constants (fixed by the dataset)
#define D      128
#define BT     32
#define LSEQ   256
#define NTOK   (BT*LSEQ)     // 8192
#define NHEAD  8
#define DK     16
#define DI     512
#define NMAX   100000
#define NLAYER 2

// ---------------- scratch (device globals; no allocation allowed) ----------------
__device__ float g_side[(size_t)NMAX * D];
__device__ float g_sum [(size_t)NMAX * D];
__device__ float g_prod[(size_t)NMAX * D];
__device__ float g_x[(size_t)NTOK * D];
__device__ float g_q[(size_t)NTOK * D];
__device__ float g_k[(size_t)NTOK * D];
__device__ float g_v[(size_t)NTOK * D];
__device__ float g_o[(size_t)NTOK * D];
__device__ float g_t[(size_t)NTOK * D];
__device__ float g_h[(size_t)NTOK * DI];

// ---------------- utility kernels ----------------
__global__ void zero_kernel(float* __restrict__ p, int n4) {
    int i = blockIdx.x * blockDim.x + threadIdx.x;
    if (i < n4) ((float4*)p)[i] = make_float4(0.f, 0.f, 0.f, 0.f);
}

__global__ void copy_kernel(const float* __restrict__ a, float* __restrict__ b, int n4) {
    int i = blockIdx.x * blockDim.x + threadIdx.x;
    if (i < n4) ((float4*)b)[i] = ((const float4*)a)[i];
}

// side elementwise: sum = ego + side, prod = ego * side
__global__ void sumprod_kernel(const float* __restrict__ ego, const float* __restrict__ side,
                               float* __restrict__ sum, float* __restrict__ prod, int n4) {
    int i = blockIdx.x * blockDim.x + threadIdx.x;
    if (i >= n4) return;
    float4 e = ((const float4*)ego)[i];
    float4 s = ((const float4*)side)[i];
    ((float4*)sum)[i]  = make_float4(e.x + s.x, e.y + s.y, e.z + s.z, e.w + s.w);
    ((float4*)prod)[i] = make_float4(e.x * s.x, e.y * s.y, e.z * s.z, e.w * s.w);
}

// ---------------- sorted-COO SpMM with run-length accumulation ----------------
#define EPB 256
__global__ __launch_bounds__(D) void spmm_kernel(
    const float* __restrict__ vals, const int* __restrict__ rows,
    const int* __restrict__ cols, const float* __restrict__ ego,
    float* __restrict__ side, int nnz)
{
    __shared__ int   s_row[EPB];
    __shared__ int   s_col[EPB];
    __shared__ float s_val[EPB];
    int e0 = blockIdx.x * EPB;
    int cnt = min(EPB, nnz - e0);
    if (cnt <= 0) return;
    for (int i = threadIdx.x; i < cnt; i += blockDim.x) {
        s_row[i] = rows[e0 + i];
        s_col[i] = cols[e0 + i];
        s_val[i] = vals[e0 + i];
    }
    __syncthreads();
    int t = threadIdx.x;                 // dimension index 0..127
    float acc = 0.f;
    int cur = s_row[0];
    for (int i = 0; i < cnt; i++) {
        int r = s_row[i];
        if (r != cur) {
            atomicAdd(&side[(size_t)cur * D + t], acc);
            acc = 0.f;
            cur = r;
        }
        acc = fmaf(s_val[i], __ldg(&ego[(size_t)s_col[i] * D + t]), acc);
    }
    atomicAdd(&side[(size_t)cur * D + t], acc);
}

// ---------------- generic fp32 tiled GEMM with fused epilogue ----------------
// C[M,N] = op(A[M,K] @ W[K,N] + bias + res) (+= existing C if accum)
// act: 0 = none, 1 = relu, 2 = leaky_relu(0.01)
#define BM 64
#define BN 64
#define BK 16
__global__ __launch_bounds__(256) void gemm_kernel(
    const float* __restrict__ A, const float* __restrict__ W,
    const float* __restrict__ bias, const float* __restrict__ res,
    float* __restrict__ C, int M, int N, int K, int act, int accum)
{
    __shared__ float As[BK][BM + 4];   // row stride 68 floats = 272B (16B aligned)
    __shared__ float Bs[BK][BN];
    int tid = threadIdx.x;
    int tx = tid & 15;                 // column group 0..15
    int ty = tid >> 4;                 // row group 0..15
    int row0 = blockIdx.y * BM;
    int col0 = blockIdx.x * BN;

    int a_r  = tid >> 2;               // 0..63
    int a_c4 = (tid & 3) * 4;          // 0,4,8,12
    int b_r  = tid >> 4;               // 0..15
    int b_c4 = (tid & 15) * 4;         // 0..60

    float acc[4][4] = {};

    for (int k0 = 0; k0 < K; k0 += BK) {
        float4 av = make_float4(0.f, 0.f, 0.f, 0.f);
        int grow = row0 + a_r;
        if (grow < M) av = *(const float4*)(A + (size_t)grow * K + k0 + a_c4);
        As[a_c4 + 0][a_r] = av.x;
        As[a_c4 + 1][a_r] = av.y;
        As[a_c4 + 2][a_r] = av.z;
        As[a_c4 + 3][a_r] = av.w;
        *(float4*)&Bs[b_r][b_c4] = *(const float4*)(W + (size_t)(k0 + b_r) * N + col0 + b_c4);
        __syncthreads();
        #pragma unroll
        for (int k = 0; k < BK; k++) {
            float4 a4 = *(const float4*)&As[k][ty * 4];
            float4 b4 = *(const float4*)&Bs[k][tx * 4];
            float a[4] = {a4.x, a4.y, a4.z, a4.w};
            float b[4] = {b4.x, b4.y, b4.z, b4.w};
            #pragma unroll
            for (int i = 0; i < 4; i++)
                #pragma unroll
                for (int j = 0; j < 4; j++)
                    acc[i][j] = fmaf(a[i], b[j], acc[i][j]);
        }
        __syncthreads();
    }

    #pragma unroll
    for (int i = 0; i < 4; i++) {
        int r = row0 + ty * 4 + i;
        if (r >= M) continue;
        #pragma unroll
        for (int j = 0; j < 4; j++) {
            int c = col0 + tx * 4 + j;
            float v = acc[i][j] + bias[c];
            if (res) v += res[(size_t)r * N + c];
            if (act == 1)      v = fmaxf(v, 0.f);
            else if (act == 2) v = (v > 0.f) ? v : 0.01f * v;
            size_t idx = (size_t)r * N + c;
            if (accum) v += C[idx];
            C[idx] = v;
        }
    }
}

// ---------------- fused attention (per (batch, head) block, online softmax) --------
__global__ __launch_bounds__(LSEQ) void attn_kernel(
    const float* __restrict__ q, const float* __restrict__ k,
    const float* __restrict__ v, float* __restrict__ o)
{
    __shared__ float Ks[LSEQ][DK];
    __shared__ float Vs[LSEQ][DK];
    int b = blockIdx.x / NHEAD;
    int h = blockIdx.x % NHEAD;
    int t = threadIdx.x;               // token index (loader + query row)

    size_t base = ((size_t)b * LSEQ + t) * D + h * DK;
    {
        const float4* kp = (const float4*)(k + base);
        const float4* vp = (const float4*)(v + base);
        float4* ksd = (float4*)Ks[t];
        float4* vsd = (float4*)Vs[t];
        #pragma unroll
        for (int i = 0; i < 4; i++) { ksd[i] = kp[i]; vsd[i] = vp[i]; }
    }
    __syncthreads();

    float qr[DK];
    {
        const float4* qp = (const float4*)(q + base);
        #pragma unroll
        for (int i = 0; i < 4; i++) {
            float4 qq = qp[i];
            qr[i*4+0] = qq.x; qr[i*4+1] = qq.y; qr[i*4+2] = qq.z; qr[i*4+3] = qq.w;
        }
    }

    float mx = -1e30f, sm = 0.f;
    float oacc[DK] = {};
    for (int m = 0; m < LSEQ; m++) {
        float s = 0.f;
        #pragma unroll
        for (int d = 0; d < DK; d++) s = fmaf(qr[d], Ks[m][d], s);
        s *= 0.25f;                    // 1/sqrt(DK)
        float nm = fmaxf(mx, s);
        float corr = __expf(mx - nm);
        float p    = __expf(s  - nm);
        sm = sm * corr + p;
        #pragma unroll
        for (int d = 0; d < DK; d++) oacc[d] = fmaf(oacc[d], corr, p * Vs[m][d]);
        mx = nm;
    }
    float inv = 1.f / sm;
    float4* op = (float4*)(o + base);
    #pragma unroll
    for (int i = 0; i < 4; i++)
        op[i] = make_float4(oacc[i*4+0]*inv, oacc[i*4+1]*inv, oacc[i*4+2]*inv, oacc[i*4+3]*inv);
}

// ---------------- LayerNorm (one warp per row of 128) ----------------
__global__ __launch_bounds__(32) void ln_kernel(
    const float* __restrict__ in, const float* __restrict__ g,
    const float* __restrict__ b, float* __restrict__ out)
{
    int row = blockIdx.x;
    int lane = threadIdx.x;
    const float4* p = (const float4*)(in + (size_t)row * D);
    float4 x = p[lane];
    float s  = x.x + x.y + x.z + x.w;
    float sq = x.x*x.x + x.y*x.y + x.z*x.z + x.w*x.w;
    #pragma unroll
    for (int off = 16; off; off >>= 1) {
        s  += __shfl_xor_sync(0xFFFFFFFFu, s,  off);
        sq += __shfl_xor_sync(0xFFFFFFFFu, sq, off);
    }
    float mean = s * (1.f / D);
    float var  = sq * (1.f / D) - mean * mean;
    float rs = rsqrtf(var + 1e-5f);
    float4 gg = ((const float4*)g)[lane];
    float4 bb = ((const float4*)b)[lane];
    float4 r;
    r.x = (x.x - mean) * rs * gg.x + bb.x;
    r.y = (x.y - mean) * rs * gg.y + bb.y;
    r.z = (x.z - mean) * rs * gg.z + bb.z;
    r.w = (x.w - mean) * rs * gg.w + bb.w;
    ((float4*)(out + (size_t)row * D))[lane] = r;
}

// ---------------- host launch ----------------
extern "C" void kernel_launch(void* const* d_in, const int* in_sizes, int n_in,
                              void* d_out, int out_size)
{
    const float* ego    = (const float*)d_in[0];
    const float* vals   = (const float*)d_in[1];
    const float* W1     = (const float*)d_in[2];
    const float* b1     = (const float*)d_in[3];
    const float* W2     = (const float*)d_in[4];
    const float* b2     = (const float*)d_in[5];
    const float* enc_in = (const float*)d_in[6];
    const float* wq     = (const float*)d_in[7];
    const float* bq     = (const float*)d_in[8];
    const float* wk     = (const float*)d_in[9];
    const float* bk     = (const float*)d_in[10];
    const float* wv     = (const float*)d_in[11];
    const float* bv     = (const float*)d_in[12];
    const float* wo     = (const float*)d_in[13];
    const float* bo     = (const float*)d_in[14];
    const float* ln1_g  = (const float*)d_in[15];
    const float* ln1_b  = (const float*)d_in[16];
    const float* cw1    = (const float*)d_in[17];
    const float* cb1    = (const float*)d_in[18];
    const float* cw2    = (const float*)d_in[19];
    const float* cb2    = (const float*)d_in[20];
    const float* ln2_g  = (const float*)d_in[21];
    const float* ln2_b  = (const float*)d_in[22];
    const int*   rows   = (const int*)d_in[23];
    const int*   cols   = (const int*)d_in[24];

    int N   = in_sizes[0] / D;
    int nnz = in_sizes[1];

    float* agg_out = (float*)d_out;
    float* x_out   = (float*)d_out + (size_t)N * D;

    float *side, *sum, *prod, *x, *q, *kk, *vv, *o, *t, *hh;
    cudaGetSymbolAddress((void**)&side, g_side);
    cudaGetSymbolAddress((void**)&sum,  g_sum);
    cudaGetSymbolAddress((void**)&prod, g_prod);
    cudaGetSymbolAddress((void**)&x,    g_x);
    cudaGetSymbolAddress((void**)&q,    g_q);
    cudaGetSymbolAddress((void**)&kk,   g_k);
    cudaGetSymbolAddress((void**)&vv,   g_v);
    cudaGetSymbolAddress((void**)&o,    g_o);
    cudaGetSymbolAddress((void**)&t,    g_t);
    cudaGetSymbolAddress((void**)&hh,   g_h);

    // ---- graph stage 1: SpMM + bi-interaction ----
    int n4 = (N * D) / 4;
    zero_kernel<<<(n4 + 255) / 256, 256>>>(side, n4);
    spmm_kernel<<<(nnz + EPB - 1) / EPB, D>>>(vals, rows, cols, ego, side, nnz);
    sumprod_kernel<<<(n4 + 255) / 256, 256>>>(ego, side, sum, prod, n4);

    dim3 gagg(D / BN, (N + BM - 1) / BM);
    gemm_kernel<<<gagg, 256>>>(sum,  W1, b1, nullptr, agg_out, N, D, D, 2, 0);
    gemm_kernel<<<gagg, 256>>>(prod, W2, b2, nullptr, agg_out, N, D, D, 2, 1);

    // ---- graph stage 2: transformer encoder ----
    copy_kernel<<<(NTOK * D / 4 + 255) / 256, 256>>>(enc_in, x, NTOK * D / 4);

    dim3 g1(D / BN, NTOK / BM);   // [8192,128] x [128,128]
    dim3 g2(DI / BN, NTOK / BM);  // [8192,512]
    for (int i = 0; i < NLAYER; i++) {
        const float* wq_i = wq + (size_t)i * D * D;
        const float* wk_i = wk + (size_t)i * D * D;
        const float* wv_i = wv + (size_t)i * D * D;
        const float* wo_i = wo + (size_t)i * D * D;
        const float* cw1_i = cw1 + (size_t)i * D * DI;
        const float* cw2_i = cw2 + (size_t)i * DI * D;

        gemm_kernel<<<g1, 256>>>(x, wq_i, bq + i * D, nullptr, q,  NTOK, D, D, 0, 0);
        gemm_kernel<<<g1, 256>>>(x, wk_i, bk + i * D, nullptr, kk, NTOK, D, D, 0, 0);
        gemm_kernel<<<g1, 256>>>(x, wv_i, bv + i * D, nullptr, vv, NTOK, D, D, 0, 0);

        attn_kernel<<<BT * NHEAD, LSEQ>>>(q, kk, vv, o);

        gemm_kernel<<<g1, 256>>>(o, wo_i, bo + i * D, x, t, NTOK, D, D, 0, 0);
        ln_kernel<<<NTOK, 32>>>(t, ln1_g + i * D, ln1_b + i * D, x);

        gemm_kernel<<<g2, 256>>>(x, cw1_i, cb1 + i * DI, nullptr, hh, NTOK, DI, D, 1, 0);
        gemm_kernel<<<g1, 256>>>(hh, cw2_i, cb2 + i * D, x, t, NTOK, D, DI, 0, 0);

        float* lnout = (i == NLAYER - 1) ? x_out : x;
        ln_kernel<<<NTOK, 32>>>(t, ln2_g + i * D, ln2_b + i * D, lnout);
    }
}